// round 7
// baseline (speedup 1.0000x reference)
#include <cuda_runtime.h>
#include <cstdint>

#define P_GAIN     2.0f
#define P_BASELINE 100.0f
static constexpr int B = 32;
static constexpr int E = 64;
static constexpr int H = 128;
static constexpr int W = 128;
static constexpr int R = 13;
static constexpr int D = 32;
static constexpr int HALF = R / 2;
static constexpr int PIX = H * W;               // 16384
static constexpr int NPX = R * R;               // 169 patch pixels
static constexpr int PPAD = 176;                // padded patch stride
static constexpr int BAND = 8;                  // rows per band
static constexpr int NBAND = H / BAND;          // 16
static constexpr int BAND_F4 = BAND * W / 4;    // 256 float4 per band
static constexpr int BAND_BYTES = BAND * W * 4; // 4096
static constexpr int NSPLIT = 8;                // emitter splits per z-slice
static constexpr int ESPLIT = 2;                // emitter splits in render
static constexpr int EHALF = E / ESPLIT;        // 32

// Scratch (static device globals — no allocation)
__device__ float g_patch[B * E * PPAD];         // 1.44 MB pre-scaled patches
__device__ int2  g_rc[B * E];                   // (r0, c0) per emitter

// ---------------------------------------------------------------------------
// Kernel 1: z-grouped patch precompute.
// Block = (z, split). Stages the full 43KB coeff slice [169][64] into smem
// with coalesced float4 loads (slice read only NSPLIT times total -> ~11MB L2),
// builds the list of emitters with zi==z && (e%NSPLIT)==split, then for each:
// 64 weights (incl. amp) -> smem, 169 threads do conflict-free smem dots.
// ---------------------------------------------------------------------------
__global__ __launch_bounds__(256) void patch_kernel(const float* __restrict__ xyz,
                                                    const float* __restrict__ nph,
                                                    const float* __restrict__ coeff)
{
    const int z     = blockIdx.x;    // 0..D-1
    const int split = blockIdx.y;    // 0..NSPLIT-1
    const int t     = threadIdx.x;

    __shared__ float s_sl[NPX * 65];     // 43.9 KB padded slice [169][65]
    __shared__ float s_w[64];            // weights*amp for current emitter
    __shared__ int   s_list[256];
    __shared__ int   s_n;

    if (t == 0) s_n = 0;

    // ---- stage slice (coalesced float4) ----
    const float4* __restrict__ c4 =
        reinterpret_cast<const float4*>(coeff + (size_t)z * NPX * 64);
    for (int i4 = t; i4 < NPX * 16; i4 += 256) {   // 2704 float4
        const float4 f = c4[i4];
        const int pix = i4 >> 4;
        const int k   = (i4 & 15) * 4;
        float* s = &s_sl[pix * 65 + k];
        s[0] = f.x; s[1] = f.y; s[2] = f.z; s[3] = f.w;
    }
    __syncthreads();   // also covers s_n = 0

    // ---- build emitter list for this (z, split) ----
    for (int e = t; e < B * E; e += 256) {
        if ((e & (NSPLIT - 1)) != split) continue;
        const float zv = xyz[e * 3 + 2];
        float zc = fminf(fmaxf(zv, 0.0f), (float)(D - 1) - 1e-6f);
        if ((int)floorf(zc) == z) s_list[atomicAdd(&s_n, 1)] = e;
    }
    __syncthreads();

    const int n = s_n;
    for (int i = 0; i < n; ++i) {
        const int ge = s_list[i];
        if (t < 64) {
            const float x = xyz[ge * 3 + 0];
            const float y = xyz[ge * 3 + 1];
            const float zv = xyz[ge * 3 + 2];
            const float xf = floorf(x);
            const float yf = floorf(y);
            const float dx = x - xf;
            const float dy = y - yf;
            float zc = fminf(fmaxf(zv, 0.0f), (float)(D - 1) - 1e-6f);
            const float dz = zc - floorf(zc);

            float pw[4], qw[4], rw[4];
            pw[0] = 1.0f; pw[1] = dx; pw[2] = dx * dx; pw[3] = pw[2] * dx;
            qw[0] = 1.0f; qw[1] = dy; qw[2] = dy * dy; qw[3] = qw[2] * dy;
            rw[0] = 1.0f; rw[1] = dz; rw[2] = dz * dz; rw[3] = rw[2] * dz;
            const float amp = nph[ge] * P_GAIN;
            // k = a*16 + b*4 + c  (z,y,x order, matching coeff layout)
            s_w[t] = rw[t >> 4] * qw[(t >> 2) & 3] * pw[t & 3] * amp;
            if (t == 0) g_rc[ge] = make_int2((int)yf - HALF, (int)xf - HALF);
        }
        __syncthreads();

        if (t < NPX) {
            const float* __restrict__ row = &s_sl[t * 65];
            float sum = 0.0f;
            #pragma unroll
            for (int k = 0; k < 64; ++k)
                sum = fmaf(row[k], s_w[k], sum);
            g_patch[(size_t)ge * PPAD + t] = sum;
        }
        __syncthreads();
    }
}

// ---------------------------------------------------------------------------
// Kernel 2: render. Block = (band, frame, emitter-split): 32 emitters, 8 rows.
// Loads+scales bg band to smem once. Miss emitters -> cp.async.bulk 4KB
// smem->gmem (TMA). Hit emitters -> per-thread float4 STG with patch add
// from g_patch. JAX semantics: negative scatter targets wrap (+H/+W),
// targets >= H/W dropped.
// ---------------------------------------------------------------------------
__global__ __launch_bounds__(256) void render_kernel(const float* __restrict__ bg,
                                                     float* __restrict__ out)
{
    const int band  = blockIdx.x;            // 0..NBAND-1
    const int frame = blockIdx.y;            // 0..B-1
    const int esp   = blockIdx.z;            // 0..ESPLIT-1
    const int bs    = band * BAND;
    const int t     = threadIdx.x;

    __shared__ float4 s_bg[BAND_F4];         // 4 KB scaled bg band
    __shared__ int    s_r0[EHALF];
    __shared__ int    s_c0[EHALF];
    __shared__ unsigned char s_hit[EHALF];
    __shared__ int    s_list[EHALF];
    __shared__ int    s_nhit;

    if (t == 0) s_nhit = 0;

    // ---- load + scale bg band ----
    {
        const float4 b4 = reinterpret_cast<const float4*>(
            bg + (size_t)frame * PIX + (size_t)bs * W)[t];
        float4 v;
        v.x = fmaf(b4.x, P_GAIN, P_BASELINE);
        v.y = fmaf(b4.y, P_GAIN, P_BASELINE);
        v.z = fmaf(b4.z, P_GAIN, P_BASELINE);
        v.w = fmaf(b4.w, P_GAIN, P_BASELINE);
        s_bg[t] = v;
    }
    __syncthreads();

    // ---- classify this split's 32 emitters ----
    if (t < EHALF) {
        const int ge = frame * E + esp * EHALF + t;
        const int2 rc = g_rc[ge];
        s_r0[t] = rc.x;
        s_c0[t] = rc.y;
        int hit = 0;
        #pragma unroll
        for (int lr = 0; lr < BAND; ++lr) {
            int rr = bs + lr - rc.x;
            if (rr >= H) rr -= H;            // wrapped negative target row
            if ((unsigned)rr < (unsigned)R) hit = 1;
        }
        s_hit[t] = (unsigned char)hit;
        if (hit) s_list[atomicAdd(&s_nhit, 1)] = t;
    }
    __syncthreads();

    // ---- miss emitters: TMA bulk smem->gmem band copies ----
    if (t == 0) {
        asm volatile("fence.proxy.async.shared::cta;" ::: "memory");
        uint32_t src;
        asm("{ .reg .u64 tmp; cvta.to.shared.u64 tmp, %1; cvt.u32.u64 %0, tmp; }"
            : "=r"(src) : "l"(s_bg));
        #pragma unroll 1
        for (int e2 = 0; e2 < EHALF; ++e2) {
            if (!s_hit[e2]) {
                float* dst = out + (size_t)(frame * E + esp * EHALF + e2) * PIX
                                 + (size_t)bs * W;
                asm volatile(
                    "cp.async.bulk.global.shared::cta.bulk_group [%0], [%1], %2;"
                    :: "l"(dst), "r"(src), "r"((unsigned)BAND_BYTES) : "memory");
            }
        }
        asm volatile("cp.async.bulk.commit_group;" ::: "memory");
    }

    // ---- hit emitters: per-thread float4 STG with patch add ----
    const float4 base_v = s_bg[t];
    const int pix = t * 4;
    const int lr  = pix >> 7;                // local row (W == 128), warp-uniform
    const int col = pix & (W - 1);
    const int nhit = s_nhit;

    #pragma unroll 1
    for (int kk = 0; kk < nhit; ++kk) {
        const int em = s_list[kk];
        const int ge = frame * E + esp * EHALF + em;
        const int r0 = s_r0[em];
        const int c0 = s_c0[em];
        float4 v = base_v;

        int rr = bs + lr - r0;
        if (rr >= H) rr -= H;                // wrapped negative target row
        if ((unsigned)rr < (unsigned)R) {
            const float* __restrict__ pp = g_patch + (size_t)ge * PPAD + rr * R;
            float* vp = &v.x;
            #pragma unroll
            for (int j = 0; j < 4; ++j) {
                int cj = col - c0 + j;
                if (cj >= W) cj -= W;        // wrapped negative target col
                if ((unsigned)cj < (unsigned)R) vp[j] += pp[cj];
            }
        }
        reinterpret_cast<float4*>(
            out + (size_t)ge * PIX + (size_t)bs * W)[t] = v;
    }

    // ---- drain bulk stores before smem is released ----
    if (t == 0) {
        asm volatile("cp.async.bulk.wait_group 0;" ::: "memory");
    }
}

// ---------------------------------------------------------------------------
// Launch. Inputs identified by element count:
//   xyz [B,E,3]=6144, n_photons [B,E]=2048, bg [B,H,W]=524288,
//   coeff [D,R,R,4,4,4]=346112.  Output: [B,E,H,W] f32.
// ---------------------------------------------------------------------------
extern "C" void kernel_launch(void* const* d_in, const int* in_sizes, int n_in,
                              void* d_out, int out_size)
{
    const float* xyz   = nullptr;
    const float* nph   = nullptr;
    const float* bg    = nullptr;
    const float* coeff = nullptr;
    for (int i = 0; i < n_in; ++i) {
        switch (in_sizes[i]) {
            case B * E * 3:      xyz   = (const float*)d_in[i]; break;
            case B * E:          nph   = (const float*)d_in[i]; break;
            case B * H * W:      bg    = (const float*)d_in[i]; break;
            case D * R * R * 64: coeff = (const float*)d_in[i]; break;
        }
    }
    float* out = (float*)d_out;

    dim3 pgrid(D, NSPLIT);
    patch_kernel<<<pgrid, 256>>>(xyz, nph, coeff);

    dim3 rgrid(NBAND, B, ESPLIT);
    render_kernel<<<rgrid, 256>>>(bg, out);
}

// round 8
// speedup vs baseline: 1.2131x; 1.2131x over previous
#include <cuda_runtime.h>
#include <cstdint>

#define P_GAIN     2.0f
#define P_BASELINE 100.0f
static constexpr int B = 32;
static constexpr int E = 64;
static constexpr int H = 128;
static constexpr int W = 128;
static constexpr int R = 13;
static constexpr int D = 32;
static constexpr int HALF = R / 2;
static constexpr int PIX = H * W;               // 16384
static constexpr int NPX = R * R;               // 169 patch pixels
static constexpr int PPAD = 176;                // padded patch stride
static constexpr int SLPAD = 68;                // slice row pad (16B aligned, conflict-free)
static constexpr int BAND = 8;                  // rows per band
static constexpr int NBAND = H / BAND;          // 16
static constexpr int BAND_F4 = BAND * W / 4;    // 256 float4 per band
static constexpr int BAND_BYTES = BAND * W * 4; // 4096
static constexpr int NSPLIT = 8;                // emitter splits per z-slice
static constexpr int ESPLIT = 4;                // emitter splits in render
static constexpr int EPB = E / ESPLIT;          // 16 emitters per render block

// Scratch (static device globals — no allocation)
__device__ float g_patch[B * E * PPAD];         // 1.44 MB pre-scaled patches
__device__ int2  g_rc[B * E];                   // (r0, c0) per emitter

// ---------------------------------------------------------------------------
// Kernel 1: z-grouped patch precompute, FLAT task loop (no per-emitter serial
// rounds). Block = (z, split). Stages the 43KB coeff slice [169][64] into
// smem (rows padded to 68 floats -> aligned LDS.128, conflict-free), builds
// the emitter list for this (z,split), then all 256 threads sweep tasks
// (emitter, pixel) with exactly one barrier in between.
// ---------------------------------------------------------------------------
__global__ __launch_bounds__(256) void patch_kernel(const float* __restrict__ xyz,
                                                    const float* __restrict__ nph,
                                                    const float* __restrict__ coeff)
{
    const int z     = blockIdx.x;    // 0..D-1
    const int split = blockIdx.y;    // 0..NSPLIT-1
    const int t     = threadIdx.x;

    __shared__ float s_sl[NPX * SLPAD];  // 45.97 KB padded slice
    __shared__ int   s_list[256];
    __shared__ int   s_n;

    if (t == 0) s_n = 0;

    // ---- stage slice (coalesced float4 in, aligned STS.128 out) ----
    const float4* __restrict__ c4 =
        reinterpret_cast<const float4*>(coeff + (size_t)z * NPX * 64);
    #pragma unroll 4
    for (int i4 = t; i4 < NPX * 16; i4 += 256) {   // 2704 float4
        const float4 f = c4[i4];
        const int pix = i4 >> 4;
        const int k4  = i4 & 15;
        reinterpret_cast<float4*>(&s_sl[pix * SLPAD])[k4] = f;
    }

    // ---- build emitter list for this (z, split); also write g_rc ----
    for (int e = t; e < B * E; e += 256) {
        if ((e & (NSPLIT - 1)) != split) continue;
        const float zv = xyz[e * 3 + 2];
        float zc = fminf(fmaxf(zv, 0.0f), (float)(D - 1) - 1e-6f);
        if ((int)floorf(zc) == z) {
            s_list[atomicAdd(&s_n, 1)] = e;
            const float x = xyz[e * 3 + 0];
            const float y = xyz[e * 3 + 1];
            g_rc[e] = make_int2((int)floorf(y) - HALF, (int)floorf(x) - HALF);
        }
    }
    __syncthreads();

    // ---- flat task loop: task = (listed emitter, patch pixel) ----
    const int n = s_n;
    const int work = n * NPX;
    for (int i = t; i < work; i += 256) {
        const int h  = i / NPX;
        const int p  = i - h * NPX;
        const int ge = s_list[h];

        // per-task emitter params (warp-broadcast L1 hits: same ge for ~169
        // consecutive tasks)
        const float x  = xyz[ge * 3 + 0];
        const float y  = xyz[ge * 3 + 1];
        const float zv = xyz[ge * 3 + 2];
        const float dx = x - floorf(x);
        const float dy = y - floorf(y);
        float zc = fminf(fmaxf(zv, 0.0f), (float)(D - 1) - 1e-6f);
        const float dz = zc - floorf(zc);
        const float amp = nph[ge] * P_GAIN;

        float pxv[4], pyv[4], pzv[4];
        pxv[0] = 1.0f; pxv[1] = dx; pxv[2] = dx * dx; pxv[3] = pxv[2] * dx;
        pyv[0] = 1.0f; pyv[1] = dy; pyv[2] = dy * dy; pyv[3] = pyv[2] * dy;
        pzv[0] = 1.0f; pzv[1] = dz; pzv[2] = dz * dz; pzv[3] = pzv[2] * dz;

        const float4* __restrict__ row4 =
            reinterpret_cast<const float4*>(&s_sl[p * SLPAD]);

        float sum = 0.0f;
        #pragma unroll
        for (int k4 = 0; k4 < 16; ++k4) {     // k4 = a*4 + b  (z,y)
            const float wzy = pzv[k4 >> 2] * pyv[k4 & 3];
            const float4 f = row4[k4];
            float sc = f.x;
            sc = fmaf(f.y, pxv[1], sc);
            sc = fmaf(f.z, pxv[2], sc);
            sc = fmaf(f.w, pxv[3], sc);
            sum = fmaf(sc, wzy, sum);
        }
        g_patch[(size_t)ge * PPAD + p] = sum * amp;
    }
}

// ---------------------------------------------------------------------------
// Kernel 2: render. Block = (band, frame, emitter-split/4): 16 emitters,
// 8 rows. Miss emitters -> cp.async.bulk 4KB smem->gmem, issued by thread
// t==em (distributed, per-thread commit/wait). Hit emitters -> per-thread
// float4 STG with patch add from g_patch. JAX semantics: negative scatter
// targets wrap (+H/+W), targets >= H/W dropped.
// ---------------------------------------------------------------------------
__global__ __launch_bounds__(256) void render_kernel(const float* __restrict__ bg,
                                                     float* __restrict__ out)
{
    const int band  = blockIdx.x;            // 0..NBAND-1
    const int frame = blockIdx.y;            // 0..B-1
    const int esp   = blockIdx.z;            // 0..ESPLIT-1
    const int bs    = band * BAND;
    const int t     = threadIdx.x;

    __shared__ float4 s_bg[BAND_F4];         // 4 KB scaled bg band
    __shared__ int    s_r0[EPB];
    __shared__ int    s_c0[EPB];
    __shared__ unsigned char s_hit[EPB];
    __shared__ int    s_list[EPB];
    __shared__ int    s_nhit;

    if (t == 0) s_nhit = 0;

    // ---- load + scale bg band ----
    {
        const float4 b4 = reinterpret_cast<const float4*>(
            bg + (size_t)frame * PIX + (size_t)bs * W)[t];
        float4 v;
        v.x = fmaf(b4.x, P_GAIN, P_BASELINE);
        v.y = fmaf(b4.y, P_GAIN, P_BASELINE);
        v.z = fmaf(b4.z, P_GAIN, P_BASELINE);
        v.w = fmaf(b4.w, P_GAIN, P_BASELINE);
        s_bg[t] = v;
    }
    __syncthreads();

    // ---- classify this split's 16 emitters ----
    if (t < EPB) {
        const int ge = frame * E + esp * EPB + t;
        const int2 rc = g_rc[ge];
        s_r0[t] = rc.x;
        s_c0[t] = rc.y;
        int hit = 0;
        #pragma unroll
        for (int lr = 0; lr < BAND; ++lr) {
            int rr = bs + lr - rc.x;
            if (rr >= H) rr -= H;            // wrapped negative target row
            if ((unsigned)rr < (unsigned)R) hit = 1;
        }
        s_hit[t] = (unsigned char)hit;
        if (hit) s_list[atomicAdd(&s_nhit, 1)] = t;
    }
    __syncthreads();

    // ---- miss emitters: distributed TMA bulk copies (thread t == emitter) ----
    const bool issuer = (t < EPB) && !s_hit[t];
    if (issuer) {
        asm volatile("fence.proxy.async.shared::cta;" ::: "memory");
        uint32_t src;
        asm("{ .reg .u64 tmp; cvta.to.shared.u64 tmp, %1; cvt.u32.u64 %0, tmp; }"
            : "=r"(src) : "l"(s_bg));
        float* dst = out + (size_t)(frame * E + esp * EPB + t) * PIX
                         + (size_t)bs * W;
        asm volatile(
            "cp.async.bulk.global.shared::cta.bulk_group [%0], [%1], %2;"
            :: "l"(dst), "r"(src), "r"((unsigned)BAND_BYTES) : "memory");
        asm volatile("cp.async.bulk.commit_group;" ::: "memory");
    }

    // ---- hit emitters: per-thread float4 STG with patch add ----
    const float4 base_v = s_bg[t];
    const int pix = t * 4;
    const int lr  = pix >> 7;                // local row (W == 128), warp-uniform
    const int col = pix & (W - 1);
    const int nhit = s_nhit;

    #pragma unroll 1
    for (int kk = 0; kk < nhit; ++kk) {
        const int em = s_list[kk];
        const int ge = frame * E + esp * EPB + em;
        const int r0 = s_r0[em];
        const int c0 = s_c0[em];
        float4 v = base_v;

        int rr = bs + lr - r0;
        if (rr >= H) rr -= H;                // wrapped negative target row
        if ((unsigned)rr < (unsigned)R) {
            const float* __restrict__ pp = g_patch + (size_t)ge * PPAD + rr * R;
            float* vp = &v.x;
            #pragma unroll
            for (int j = 0; j < 4; ++j) {
                int cj = col - c0 + j;
                if (cj >= W) cj -= W;        // wrapped negative target col
                if ((unsigned)cj < (unsigned)R) vp[j] += pp[cj];
            }
        }
        reinterpret_cast<float4*>(
            out + (size_t)ge * PIX + (size_t)bs * W)[t] = v;
    }

    // ---- each issuer drains its own bulk copy before exiting ----
    if (issuer) {
        asm volatile("cp.async.bulk.wait_group 0;" ::: "memory");
    }
}

// ---------------------------------------------------------------------------
// Launch. Inputs identified by element count:
//   xyz [B,E,3]=6144, n_photons [B,E]=2048, bg [B,H,W]=524288,
//   coeff [D,R,R,4,4,4]=346112.  Output: [B,E,H,W] f32.
// ---------------------------------------------------------------------------
extern "C" void kernel_launch(void* const* d_in, const int* in_sizes, int n_in,
                              void* d_out, int out_size)
{
    const float* xyz   = nullptr;
    const float* nph   = nullptr;
    const float* bg    = nullptr;
    const float* coeff = nullptr;
    for (int i = 0; i < n_in; ++i) {
        switch (in_sizes[i]) {
            case B * E * 3:      xyz   = (const float*)d_in[i]; break;
            case B * E:          nph   = (const float*)d_in[i]; break;
            case B * H * W:      bg    = (const float*)d_in[i]; break;
            case D * R * R * 64: coeff = (const float*)d_in[i]; break;
        }
    }
    float* out = (float*)d_out;

    dim3 pgrid(D, NSPLIT);
    patch_kernel<<<pgrid, 256>>>(xyz, nph, coeff);

    dim3 rgrid(NBAND, B, ESPLIT);
    render_kernel<<<rgrid, 256>>>(bg, out);
}